// round 7
// baseline (speedup 1.0000x reference)
#include <cuda_runtime.h>
#include <cuda_bf16.h>

// ParametricInterpolation, round 6.
//
// Structure (collapsed from the O(N^2) reference):
//   raw_pos = i - rint(cv) is an exact integer, so new_pos is integer and the
//   exp(-diff^4) soft gather is a constant-weight FIR:
//     k1 nonzero at j-m in [-2,2]  with weights {e^-16, e^-1, 1, e^-1, e^-16}
//     k2 nonzero at j-m in [-3,1]  (same weights shifted by -1)
//   (e^-81 = 6.6e-36 sits below 1 ulp of every f32 partial sum -> bit-neutral.)
//
// Numerics history: FMA-asc (R1=R5), mul/add-asc (R2), and exact-f64 (R4) cv
// all flip the SAME ~2 rint decisions vs golden => the golden perturbation is
// upstream of the dot. Remaining suspect: XLA's algebraic simplifier rewrites
// divide-by-constant into multiply-by-reciprocal (params * rn32(1/SCALER)),
// a known 1-ulp deviation from IEEE division. This round reproduces that:
//   p_k = rn( pb[k] * rn(1/scaler_k) ),  reciprocal = IEEE rn as XLA folds it.

#ifndef SIG_LEN
#define SIG_LEN 2048
#endif

__global__ void ParametricInterpolation_kernel(
    const float* __restrict__ x,       // [B, N]
    const float* __restrict__ params,  // [B, 5]
    float* __restrict__ out,           // [B, N]
    float* __restrict__ curve,         // [B, N] or nullptr
    int B)
{
    const int N = SIG_LEN;
    int gid = blockIdx.x * blockDim.x + threadIdx.x;
    if (gid >= B * N) return;
    int b = gid >> 11;          // / 2048
    int i = gid & (N - 1);      // % 2048

    // XLA-style divide-by-constant: multiply by the IEEE-rounded reciprocal
    // of the f32 scaler constant (constant-folded rn(1.0f / 1e11f), etc.).
    const float r0 = __fdiv_rn(1.0f, 1e11f);
    const float r1 = __fdiv_rn(1.0f, 1e7f);
    const float r2 = __fdiv_rn(1.0f, 1e3f);

    const float* pb = params + b * 5;
    float p0 = __fmul_rn(pb[0], r0);
    float p1 = __fmul_rn(pb[1], r1);
    float p2 = __fmul_rn(pb[2], r2);
    float p3 = pb[3];               // / 1.0 exact
    float p4 = pb[4];

    // integer_pow by squaring, forced rn multiplies.
    float t  = (float)i;
    float t2 = __fmul_rn(t, t);     // exact (i < 2^11)
    float t3 = __fmul_rn(t2, t);    // rn(t^3)
    float t4 = __fmul_rn(t2, t2);   // rn(t^4)

    // k-ascending FMA dot (XLA fused-loop lowering with fp contraction).
    float cv = fmaf(p0, t4, 0.0f);
    cv = fmaf(p1, t3, cv);
    cv = fmaf(p2, t2, cv);
    cv = fmaf(p3, t,  cv);
    cv = __fadd_rn(cv, p4);

    float ci = rintf(cv);           // round-half-to-even == jnp.round
    float d  = __fadd_rn(cv, -ci);  // exact (Sterbenz)

    // raw_pos = t - ci: exact integer; clip to [1, 2047].
    float raw_pos = __fadd_rn(t, -ci);
    float np_f = fminf(fmaxf(raw_pos, 1.0f), 2047.0f);
    int m = (int)np_f;

    // Constant-weight gather, ascending-j order to mirror reference partials.
    const float W1 = 0.36787944117144233f;    // f32(exp(-1))
    const float W2 = 1.1253517471925912e-07f; // f32(exp(-16))

    const float* xrow = x + b * N;
    float s1 = 0.0f, w1s = 0.0f, s2 = 0.0f, w2s = 0.0f;

    #pragma unroll
    for (int o = -3; o <= 2; o++) {
        int j = m + o;
        if (j < 0 || j >= N) continue;
        float xv = __ldg(xrow + j);
        float wk1 = (o == 0) ? 1.0f
                  : (o == -1 || o == 1) ? W1
                  : (o == -2 || o == 2) ? W2 : 0.0f;
        int o2 = o + 1;
        float wk2 = (o2 == 0) ? 1.0f
                  : (o2 == -1 || o2 == 1) ? W1
                  : (o2 == -2 || o2 == 2) ? W2 : 0.0f;
        s1  = fmaf(xv, wk1, s1);
        w1s = __fadd_rn(w1s, wk1);
        s2  = fmaf(xv, wk2, s2);
        w2s = __fadd_rn(w2s, wk2);
    }

    float a1 = __fdiv_rn(s1, w1s);
    float a2 = __fdiv_rn(s2, w2s);

    // out = a1*(1-d) + a2*d
    float one_md = __fadd_rn(1.0f, -d);
    float o_val = __fadd_rn(__fmul_rn(a1, one_md), __fmul_rn(a2, d));

    out[gid] = o_val;
    if (curve) curve[gid] = cv;
}

extern "C" void kernel_launch(void* const* d_in, const int* in_sizes, int n_in,
                              void* d_out, int out_size)
{
    const float* x      = (const float*)d_in[0];   // [B, 2048] f32
    const float* params = (const float*)d_in[1];   // [B, 5]    f32
    float* out = (float*)d_out;

    int B = in_sizes[1] / 5;           // 16
    int total = B * SIG_LEN;           // 32768

    float* curve = (out_size >= 2 * total) ? (out + total) : nullptr;

    int threads = 256;
    int blocks = (total + threads - 1) / threads;  // 128
    ParametricInterpolation_kernel<<<blocks, threads>>>(x, params, out, curve, B);
}